// round 11
// baseline (speedup 1.0000x reference)
#include <cuda_runtime.h>
#include <cuda_fp16.h>
#include <cstdint>

#define N_PIX 131072
#define W_PIX 8192
#define EPS_BN 1e-5f
#define SB128 272
#define SB256 528

// ------------------------- device scratch -------------------------
__device__ __half g_xHi[(size_t)N_PIX * 128];
__device__ __half g_xLo[(size_t)N_PIX * 128];
__device__ __half g_catHi[(size_t)N_PIX * 256];  // [n][0:128)=r, [128:256)=h
__device__ __half g_hLo[(size_t)N_PIX * 128];
__device__ __half g_bfHi[256 * 128], g_bfLo[256 * 128];   // rows 0-127 reg1, 128-255 cl1
__device__ __half g_bmHi[128 * 128], g_bmLo[128 * 128];   // cl2
__device__ __half g_bcHi[128 * 128], g_bcLo[128 * 128];   // cl3[0:128]
__device__ __half g_w2h[256 * 256];                       // w2cat[s*32+o][f]
__device__ float  g_alphaF[256], g_betaF[256];
__device__ int    g_inds[N_PIX];

__device__ __forceinline__ float lrelu_f(float v) { return v >= 0.f ? v : 0.01f * v; }
__device__ __forceinline__ uint32_t smem_u32(const void* p) {
    uint32_t a;
    asm("{ .reg .u64 t; cvta.to.shared.u64 t, %1; cvt.u32.u64 %0, t; }" : "=r"(a) : "l"(p));
    return a;
}
__device__ __forceinline__ uint32_t ford(float f) {
    uint32_t u = __float_as_uint(f);
    return (u & 0x80000000u) ? ~u : (u | 0x80000000u);
}

#define CP_ASYNC16(dst, src) \
    asm volatile("cp.async.cg.shared.global [%0], [%1], 16;" :: "r"(dst), "l"(src) : "memory")
#define CP_COMMIT() asm volatile("cp.async.commit_group;" ::: "memory")
#define CP_WAIT0()  asm volatile("cp.async.wait_group 0;" ::: "memory")
#define LDSM_X4(r, addr) \
    asm volatile("ldmatrix.sync.aligned.m8n8.x4.shared.b16 {%0,%1,%2,%3}, [%4];" \
        : "=r"((r)[0]), "=r"((r)[1]), "=r"((r)[2]), "=r"((r)[3]) : "r"(addr))
#define MMAF16(d, a, b) \
    asm volatile("mma.sync.aligned.m16n8k16.row.col.f32.f16.f16.f32 " \
        "{%0,%1,%2,%3},{%4,%5,%6,%7},{%8,%9},{%0,%1,%2,%3};" \
        : "+f"((d)[0]), "+f"((d)[1]), "+f"((d)[2]), "+f"((d)[3]) \
        : "r"((a)[0]), "r"((a)[1]), "r"((a)[2]), "r"((a)[3]), "r"((b)[0]), "r"((b)[1]))

// warp tile 32px x 64out over KH k, full-K-resident smem, optional 3-product split
template<int KH, int SB, bool P3>
__device__ __forceinline__ void run_pass32(float (&acc)[2][8][4],
    uint32_t aHiB, uint32_t aLoB, uint32_t bHiB, uint32_t bLoB, int lane)
{
    const uint32_t aOff = (uint32_t)((lane & 15) * SB + (lane >> 4) * 16);
    const uint32_t bOff = (uint32_t)(((lane & 7) + ((lane >> 4) & 1) * 8) * SB +
                                     ((lane >> 3) & 1) * 16);
#pragma unroll
    for (int kk = 0; kk < KH / 16; kk++) {
        uint32_t ah0[4], ah1[4], al0[4], al1[4];
        LDSM_X4(ah0, aHiB + aOff + kk * 32);
        LDSM_X4(ah1, aHiB + aOff + 16u * SB + kk * 32);
        if (P3) {
            LDSM_X4(al0, aLoB + aOff + kk * 32);
            LDSM_X4(al1, aLoB + aOff + 16u * SB + kk * 32);
        }
#pragma unroll
        for (int np = 0; np < 4; np++) {
            uint32_t bh[4];
            LDSM_X4(bh, bHiB + bOff + (uint32_t)(np * 16 * SB) + kk * 32);
            MMAF16(acc[0][np * 2],     ah0, bh);
            MMAF16(acc[0][np * 2 + 1], ah0, bh + 2);
            MMAF16(acc[1][np * 2],     ah1, bh);
            MMAF16(acc[1][np * 2 + 1], ah1, bh + 2);
            if (P3) {
                uint32_t bl[4];
                LDSM_X4(bl, bLoB + bOff + (uint32_t)(np * 16 * SB) + kk * 32);
                MMAF16(acc[0][np * 2],     ah0, bl);
                MMAF16(acc[0][np * 2 + 1], ah0, bl + 2);
                MMAF16(acc[0][np * 2],     al0, bh);
                MMAF16(acc[0][np * 2 + 1], al0, bh + 2);
                MMAF16(acc[1][np * 2],     ah1, bl);
                MMAF16(acc[1][np * 2 + 1], ah1, bl + 2);
                MMAF16(acc[1][np * 2],     al1, bh);
                MMAF16(acc[1][np * 2 + 1], al1, bh + 2);
            }
        }
    }
}

// cp.async tile loader: rows x 128 halves, smem stride SB128
__device__ __forceinline__ void cp_tile(uint32_t dst, const __half* src,
                                        int rows, int gHalves, int tid, int nthr)
{
    int total = rows * 16;
    for (int i = tid; i < total; i += nthr) {
        int r = i >> 4, s = i & 15;
        CP_ASYNC16(dst + (uint32_t)(r * SB128 + s * 16), src + (size_t)r * gHalves + s * 8);
    }
}
// rows x 256 halves, stride SB256
__device__ __forceinline__ void cp_tile256(uint32_t dst, const __half* src,
                                           int rows, int tid, int nthr)
{
    int total = rows * 32;
    for (int i = tid; i < total; i += nthr) {
        int r = i >> 5, s = i & 31;
        CP_ASYNC16(dst + (uint32_t)(r * SB256 + s * 16), src + (size_t)r * 256 + s * 8);
    }
}

// ------------------------- prep kernels -------------------------
__global__ void prep_w(const float* __restrict__ cl1_w, const float* __restrict__ reg1_w,
                       const float* __restrict__ cl2_w, const float* __restrict__ cl3_w,
                       const float* __restrict__ w2,
                       const float* cl1_b, const float* cl1_g, const float* cl1_bt,
                       const float* cl1_m, const float* cl1_v,
                       const float* reg1_b, const float* reg1_g, const float* reg1_bt,
                       const float* reg1_m, const float* reg1_v)
{
    int idx = blockIdx.x * 256 + threadIdx.x;
    if (idx < 32768) {
        int o = idx >> 7, k = idx & 127;
        float w = (o < 128) ? reg1_w[o * 128 + k] : cl1_w[(o - 128) * 128 + k];
        __half h = __float2half_rn(w);
        g_bfHi[idx] = h; g_bfLo[idx] = __float2half_rn(w - __half2float(h));
    } else if (idx < 49152) {
        int i = idx - 32768;
        float w = cl2_w[i]; __half h = __float2half_rn(w);
        g_bmHi[i] = h; g_bmLo[i] = __float2half_rn(w - __half2float(h));
    } else if (idx < 65536) {
        int i = idx - 49152;
        float w = cl3_w[i]; __half h = __float2half_rn(w);
        g_bcHi[i] = h; g_bcLo[i] = __float2half_rn(w - __half2float(h));
    } else if (idx < 131072) {
        int i = idx - 65536;
        int so = i >> 8, f = i & 255, s = so >> 5, o = so & 31;
        g_w2h[so * 256 + f] = __float2half_rn(w2[(s * 256 + f) * 32 + o]);
    } else if (idx < 131328) {
        int o = idx - 131072;
        if (o < 128) {
            float a = reg1_g[o] * rsqrtf(reg1_v[o] + EPS_BN);
            g_alphaF[o] = a; g_betaF[o] = (reg1_b[o] - reg1_m[o]) * a + reg1_bt[o];
        } else {
            int c = o - 128;
            float a = cl1_g[c] * rsqrtf(cl1_v[c] + EPS_BN);
            g_alphaF[o] = a; g_betaF[o] = (cl1_b[c] - cl1_m[c]) * a + cl1_bt[c];
        }
    }
}

__global__ void prep_x(const float* __restrict__ x)
{
    __shared__ float t[32][33];
    int b = blockIdx.z, w0 = blockIdx.x * 32, c0 = blockIdx.y * 32;
    int tx = threadIdx.x, ty = threadIdx.y;
    const float* src = x + ((size_t)b * 128 + c0) * W_PIX + w0;
#pragma unroll
    for (int i = 0; i < 4; i++)
        t[ty + i * 8][tx] = src[(size_t)(ty + i * 8) * W_PIX + tx];
    __syncthreads();
    size_t nbase = (size_t)b * W_PIX + w0;
#pragma unroll
    for (int i = 0; i < 4; i++) {
        int wl = ty + i * 8;
        float v = t[tx][wl];
        __half h = __float2half_rn(v);
        g_xHi[(nbase + wl) * 128 + c0 + tx] = h;
        g_xLo[(nbase + wl) * 128 + c0 + tx] = __float2half_rn(v - __half2float(h));
    }
}

// ------------------------- front: x -> [r,h] -------------------------
#define F_AHI 0
#define F_ALO 34816
#define F_BHI 69632
#define F_BLO 139264
#define F_TOTAL 208896

__global__ __launch_bounds__(256, 1) void front_kernel()
{
    extern __shared__ char sm[];
    const uint32_t sb = smem_u32(sm);
    const int tid = threadIdx.x, wid = tid >> 5, lane = tid & 31;
    const int mW = wid >> 1, nB = wid & 1;     // 4 M-warps x 2 N-warps
    const int n0 = blockIdx.x * 128;

    cp_tile(sb + F_AHI, g_xHi + (size_t)n0 * 128, 128, 128, tid, 256);
    cp_tile(sb + F_ALO, g_xLo + (size_t)n0 * 128, 128, 128, tid, 256);
    cp_tile(sb + F_BHI, g_bfHi, 256, 128, tid, 256);
    cp_tile(sb + F_BLO, g_bfLo, 256, 128, tid, 256);
    CP_COMMIT(); CP_WAIT0();
    __syncthreads();

#pragma unroll 1
    for (int pass = 0; pass < 2; pass++) {
        float acc[2][8][4];
#pragma unroll
        for (int mt = 0; mt < 2; mt++)
#pragma unroll
            for (int nt = 0; nt < 8; nt++)
#pragma unroll
                for (int q = 0; q < 4; q++) acc[mt][nt][q] = 0.f;
        run_pass32<128, SB128, true>(acc,
            sb + F_AHI + mW * 32 * SB128, sb + F_ALO + mW * 32 * SB128,
            sb + F_BHI + (pass * 128 + nB * 64) * SB128,
            sb + F_BLO + (pass * 128 + nB * 64) * SB128, lane);
#pragma unroll
        for (int mt = 0; mt < 2; mt++) {
#pragma unroll
            for (int nt = 0; nt < 8; nt++) {
#pragma unroll
                for (int row = 0; row < 2; row++) {
                    int px = mW * 32 + mt * 16 + (lane >> 2) + row * 8;
                    int og = pass * 128 + nB * 64 + nt * 8 + (lane & 3) * 2;
                    float v0 = lrelu_f(g_alphaF[og]     * acc[mt][nt][row * 2]     + g_betaF[og]);
                    float v1 = lrelu_f(g_alphaF[og + 1] * acc[mt][nt][row * 2 + 1] + g_betaF[og + 1]);
                    __half2 hv = __floats2half2_rn(v0, v1);
                    *(__half2*)(g_catHi + (size_t)(n0 + px) * 256 + og) = hv;
                    if (pass == 1) {
                        *(__half2*)(g_hLo + (size_t)(n0 + px) * 128 + og - 128) =
                            __floats2half2_rn(v0 - __low2float(hv), v1 - __high2float(hv));
                    }
                }
            }
        }
    }
}

// ------------------------- midcls: h -> x2 -> argmax/mask -------------------------
#define M_AHI 0
#define M_ALO 34816
#define M_BMH 69632
#define M_BML 104448
#define M_BCH 139264
#define M_BCL 174080
#define M_KEY 208896
#define M_MW  209920
#define M_TOTAL 210432

__global__ __launch_bounds__(256, 1) void midcls_kernel(
    const float* __restrict__ cl2_b, const float* __restrict__ cl3_w,
    const float* __restrict__ cl3_b, float* __restrict__ maskOut)
{
    extern __shared__ char sm[];
    const uint32_t sb = smem_u32(sm);
    unsigned long long* sKey = (unsigned long long*)(sm + M_KEY);
    float* sMw = (float*)(sm + M_MW);
    const int tid = threadIdx.x, wid = tid >> 5, lane = tid & 31;
    const int mW = wid >> 1, nB = wid & 1;
    const int n0 = blockIdx.x * 128;

    if (tid < 128) { sKey[tid] = 0ull; sMw[tid] = cl3_w[128 * 128 + tid]; }

    cp_tile(sb + M_AHI, g_catHi + (size_t)n0 * 256 + 128, 128, 256, tid, 256);
    cp_tile(sb + M_ALO, g_hLo + (size_t)n0 * 128, 128, 128, tid, 256);
    cp_tile(sb + M_BMH, g_bmHi, 128, 128, tid, 256);
    cp_tile(sb + M_BML, g_bmLo, 128, 128, tid, 256);
    cp_tile(sb + M_BCH, g_bcHi, 128, 128, tid, 256);
    cp_tile(sb + M_BCL, g_bcLo, 128, 128, tid, 256);
    CP_COMMIT(); CP_WAIT0();
    __syncthreads();

    float acc[2][8][4];
#pragma unroll
    for (int mt = 0; mt < 2; mt++)
#pragma unroll
        for (int nt = 0; nt < 8; nt++)
#pragma unroll
            for (int q = 0; q < 4; q++) acc[mt][nt][q] = 0.f;
    run_pass32<128, SB128, true>(acc,
        sb + M_AHI + mW * 32 * SB128, sb + M_ALO + mW * 32 * SB128,
        sb + M_BMH + nB * 64 * SB128, sb + M_BML + nB * 64 * SB128, lane);
    __syncthreads();                       // all h reads done

    // write x2 hi/lo back over A
#pragma unroll
    for (int mt = 0; mt < 2; mt++) {
#pragma unroll
        for (int nt = 0; nt < 8; nt++) {
#pragma unroll
            for (int row = 0; row < 2; row++) {
                int px = mW * 32 + mt * 16 + (lane >> 2) + row * 8;
                int o  = nB * 64 + nt * 8 + (lane & 3) * 2;
                float v0 = lrelu_f(acc[mt][nt][row * 2]     + cl2_b[o]);
                float v1 = lrelu_f(acc[mt][nt][row * 2 + 1] + cl2_b[o + 1]);
                __half2 hv = __floats2half2_rn(v0, v1);
                *(__half2*)(sm + M_AHI + px * SB128 + o * 2) = hv;
                *(__half2*)(sm + M_ALO + px * SB128 + o * 2) =
                    __floats2half2_rn(v0 - __low2float(hv), v1 - __high2float(hv));
            }
        }
    }
    __syncthreads();

#pragma unroll
    for (int mt = 0; mt < 2; mt++)
#pragma unroll
        for (int nt = 0; nt < 8; nt++)
#pragma unroll
            for (int q = 0; q < 4; q++) acc[mt][nt][q] = 0.f;
    run_pass32<128, SB128, true>(acc,
        sb + M_AHI + mW * 32 * SB128, sb + M_ALO + mW * 32 * SB128,
        sb + M_BCH + nB * 64 * SB128, sb + M_BCL + nB * 64 * SB128, lane);

    // argmax (first-max-index via 255-o tiebreak)
#pragma unroll
    for (int mt = 0; mt < 2; mt++) {
#pragma unroll
        for (int row = 0; row < 2; row++) {
            int px = mW * 32 + mt * 16 + (lane >> 2) + row * 8;
            float bv = -3.4e38f; int bi = 0;
#pragma unroll
            for (int nt = 0; nt < 8; nt++) {
#pragma unroll
                for (int cc = 0; cc < 2; cc++) {
                    int o = nB * 64 + nt * 8 + (lane & 3) * 2 + cc;
                    float v = acc[mt][nt][row * 2 + cc] + cl3_b[o];
                    if (v > bv) { bv = v; bi = o; }
                }
            }
            atomicMax(&sKey[px], ((unsigned long long)ford(bv) << 32) |
                                 (unsigned long long)(255 - bi));
        }
    }
    __syncthreads();

    if (tid < 128) {
        int ind = 255 - (int)(sKey[tid] & 0xFFFFFFFFull);
        g_inds[n0 + tid] = ind;
        float m = cl3_b[128];
#pragma unroll 8
        for (int k = 0; k < 128; k++) {
            float xv = __half2float(*(__half*)(sm + M_AHI + tid * SB128 + k * 2)) +
                       __half2float(*(__half*)(sm + M_ALO + tid * SB128 + k * 2));
            m = fmaf(sMw[k], xv, m);
        }
        maskOut[n0 + tid] = lrelu_f(m);
    }
}

// ------------------------- yall: cat . w2cat^T + regression -------------------------
#define Y_A   0
#define Y_B   67584
#define Y_SI  202752
#define Y_SR  203264
#define Y_SB2 203776
#define Y_SW3 204800
#define Y_TOTAL 221184

__global__ __launch_bounds__(256, 1) void yall_kernel(
    const float* __restrict__ b2, const float* __restrict__ w3,
    const float* __restrict__ b3, float* __restrict__ outX)
{
    extern __shared__ char sm[];
    const uint32_t sb = smem_u32(sm);
    int*   sInds = (int*)(sm + Y_SI);
    float* sRed  = (float*)(sm + Y_SR);
    float* sB2   = (float*)(sm + Y_SB2);
    float* sW3   = (float*)(sm + Y_SW3);
    const int tid = threadIdx.x, wid = tid >> 5, lane = tid & 31;
    const int mW = wid >> 1, nB = wid & 1, tc = lane & 3;
    const int n0 = blockIdx.x * 128;

    if (tid < 128) { sInds[tid] = g_inds[n0 + tid]; sRed[tid] = 0.f; }
    if (tid < 256) sB2[tid] = b2[tid];
    cp_tile256(sb + Y_A, g_catHi + (size_t)n0 * 256, 128, tid, 256);
    cp_tile256(sb + Y_B, g_w2h, 256, tid, 256);
    CP_COMMIT();
    __syncthreads();                      // sInds ready
    for (int i = tid; i < 512; i += 256) {
        int px = i >> 2, q = i & 3;
        int ind = sInds[px];
        *(float4*)&sW3[px * 32 + q * 8]     = *(const float4*)&w3[ind * 32 + q * 8];
        *(float4*)&sW3[px * 32 + q * 8 + 4] = *(const float4*)&w3[ind * 32 + q * 8 + 4];
    }
    CP_WAIT0();
    __syncthreads();

#pragma unroll 1
    for (int pass = 0; pass < 2; pass++) {
        float acc[2][8][4];
#pragma unroll
        for (int mt = 0; mt < 2; mt++)
#pragma unroll
            for (int nt = 0; nt < 8; nt++)
#pragma unroll
                for (int q = 0; q < 4; q++) acc[mt][nt][q] = 0.f;
        run_pass32<256, SB256, false>(acc,
            sb + Y_A + mW * 32 * SB256, 0,
            sb + Y_B + (pass * 128 + nB * 64) * SB256, 0, lane);

        int band = pass * 2 + nB;
#pragma unroll
        for (int mt = 0; mt < 2; mt++) {
#pragma unroll
            for (int row = 0; row < 2; row++) {
                int px = mW * 32 + mt * 16 + (lane >> 2) + row * 8;
                int ind = sInds[px];
                int s = ind >> 4;
                if ((s >> 1) == band) {
                    int sl = s & 1;
                    float part = 0.f;
#pragma unroll
                    for (int t = 0; t < 4; t++) {
                        int nt = sl * 4 + t;
#pragma unroll
                        for (int cc = 0; cc < 2; cc++) {
                            int out  = pass * 128 + nB * 64 + nt * 8 + tc * 2 + cc;
                            int orel = t * 8 + tc * 2 + cc;
                            float y = lrelu_f(acc[mt][nt][row * 2 + cc] + sB2[out]);
                            part = fmaf(y, sW3[px * 32 + orel], part);
                        }
                    }
                    atomicAdd(&sRed[px], part);
                }
            }
        }
    }
    __syncthreads();
    if (tid < 128) {
        int ind = sInds[tid];
        outX[n0 + tid] = ((float)ind + sRed[tid] + b3[ind]) * (1.0f / 128.0f);
    }
}

// ------------------------- launch -------------------------
extern "C" void kernel_launch(void* const* d_in, const int* in_sizes, int n_in,
                              void* d_out, int out_size)
{
    const float* x_in     = (const float*)d_in[0];
    const float* cl1_w    = (const float*)d_in[1];
    const float* cl1_b    = (const float*)d_in[2];
    const float* cl1_bn_g = (const float*)d_in[3];
    const float* cl1_bn_b = (const float*)d_in[4];
    const float* cl1_bn_m = (const float*)d_in[5];
    const float* cl1_bn_v = (const float*)d_in[6];
    const float* cl2_w    = (const float*)d_in[7];
    const float* cl2_b    = (const float*)d_in[8];
    const float* cl3_w    = (const float*)d_in[9];
    const float* cl3_b    = (const float*)d_in[10];
    const float* reg1_w   = (const float*)d_in[11];
    const float* reg1_b   = (const float*)d_in[12];
    const float* reg1_bn_g= (const float*)d_in[13];
    const float* reg1_bn_b= (const float*)d_in[14];
    const float* reg1_bn_m= (const float*)d_in[15];
    const float* reg1_bn_v= (const float*)d_in[16];
    const float* w2       = (const float*)d_in[17];
    const float* b2       = (const float*)d_in[18];
    const float* w3       = (const float*)d_in[19];
    const float* b3       = (const float*)d_in[20];

    float* out = (float*)d_out;          // [0..N) x_real, [N..2N) mask

    cudaFuncSetAttribute(front_kernel, cudaFuncAttributeMaxDynamicSharedMemorySize, F_TOTAL);
    cudaFuncSetAttribute(midcls_kernel, cudaFuncAttributeMaxDynamicSharedMemorySize, M_TOTAL);
    cudaFuncSetAttribute(yall_kernel, cudaFuncAttributeMaxDynamicSharedMemorySize, Y_TOTAL);

    prep_w<<<513, 256>>>(cl1_w, reg1_w, cl2_w, cl3_w, w2,
                         cl1_b, cl1_bn_g, cl1_bn_b, cl1_bn_m, cl1_bn_v,
                         reg1_b, reg1_bn_g, reg1_bn_b, reg1_bn_m, reg1_bn_v);
    prep_x<<<dim3(W_PIX / 32, 4, 16), dim3(32, 8)>>>(x_in);
    front_kernel<<<N_PIX / 128, 256, F_TOTAL>>>();
    midcls_kernel<<<N_PIX / 128, 256, M_TOTAL>>>(cl2_b, cl3_w, cl3_b, out + N_PIX);
    yall_kernel<<<N_PIX / 128, 256, Y_TOTAL>>>(b2, w3, b3, out);
}